// round 1
// baseline (speedup 1.0000x reference)
#include <cuda_runtime.h>
#include <math.h>

namespace {

constexpr int EMBED   = 20;
constexpr int NFILT   = 16;
constexpr int TB      = 32;    // batch elems per CTA
constexpr int THREADS = 256;   // 8 warps = 8 filter-pairs
constexpr int FEAT    = 560;
constexpr int FSTRIDE = 561;   // odd stride -> conflict-free
constexpr int HSTRIDE = 65;

// smem layout (floats)
constexpr int SW_FLOATS = 8000;           // weights for one sequence (all 5 ksizes)
constexpr int SX_FLOATS = EMBED * 18 * TB; // 11520, max L = 18
constexpr int SW_OFS = 0;
constexpr int SX_OFS = SW_FLOATS;
constexpr int SF_OFS = SX_OFS + SX_FLOATS;
constexpr int SH_OFS = SF_OFS + TB * FSTRIDE;
constexpr int SMEM_FLOATS = SH_OFS + TB * HSTRIDE;
constexpr int SMEM_BYTES  = SMEM_FLOATS * 4;   // 158208 B

struct Params {
  const float* seq[7];
  const float* Wk[5];
  const float* lin1_w;
  const float* lin1_b;
  const float* lin2_w;
  const float* lin2_b;
  float* out;
  int B;
};

// One (sequence, ksize) conv + relu + global max for 2 filters per thread.
// sX layout: [c][l][TB], sWk layout: [f][c][j] (global layout copied verbatim).
template<int L, int K>
__device__ __forceinline__ void conv_k(const float* __restrict__ sX,
                                       const float* __restrict__ sWk,
                                       float* __restrict__ sF,
                                       int lane, int fpair, int featOfs) {
  constexpr int PAD = (K - 1) / 2;
  float acc0[L], acc1[L];
  #pragma unroll
  for (int t = 0; t < L; ++t) { acc0[t] = 0.f; acc1[t] = 0.f; }
  const int f0 = fpair * 2;
  #pragma unroll 2
  for (int c = 0; c < EMBED; ++c) {
    float xr[L];
    #pragma unroll
    for (int l = 0; l < L; ++l) xr[l] = sX[(c * L + l) * TB + lane];
    float w0[K], w1[K];
    #pragma unroll
    for (int j = 0; j < K; ++j) {
      w0[j] = sWk[(f0 * EMBED + c) * K + j];        // uniform across warp
      w1[j] = sWk[((f0 + 1) * EMBED + c) * K + j];
    }
    #pragma unroll
    for (int t = 0; t < L; ++t) {
      #pragma unroll
      for (int j = 0; j < K; ++j) {
        const int xi = t + j - PAD;                  // compile-time predicate
        if (xi >= 0 && xi < L) {
          acc0[t] = fmaf(xr[xi], w0[j], acc0[t]);
          acc1[t] = fmaf(xr[xi], w1[j], acc1[t]);
        }
      }
    }
  }
  // relu + global max  ==  max(0, max_t acc)
  float m0 = 0.f, m1 = 0.f;
  #pragma unroll
  for (int t = 0; t < L; ++t) { m0 = fmaxf(m0, acc0[t]); m1 = fmaxf(m1, acc1[t]); }
  float* fr = sF + lane * FSTRIDE + featOfs + f0;
  fr[0] = m0;
  fr[1] = m1;
}

template<int L, int S>
__device__ __forceinline__ void do_seq(const Params& p, float* sW, float* sX,
                                       float* sF, int tid, int lane, int fpair,
                                       int bbase) {
  // --- stage x tile, transposed to [c][l][b], folding the /5 scale ---
  const float* xg = p.seq[S];
  constexpr int CL = EMBED * L;
  for (int idx = tid; idx < CL * TB; idx += THREADS) {
    const int b   = idx / CL;
    const int rem = idx - b * CL;   // c*L + l
    int bg = bbase + b;
    if (bg >= p.B) bg = p.B - 1;    // B is a multiple of TB; safety clamp only
    sX[rem * TB + b] = xg[(size_t)bg * CL + rem] * 0.2f;
  }
  // --- stage this sequence's weights for all 5 kernel sizes ---
  constexpr int KS_[5]   = {1, 3, 5, 7, 9};
  constexpr int KOFS_[5] = {0, 320, 1280, 2880, 5120};
  #pragma unroll
  for (int kidx = 0; kidx < 5; ++kidx) {
    const int k   = KS_[kidx];
    const int cnt = NFILT * EMBED * k;
    const float* wg = p.Wk[kidx] + (size_t)S * cnt;
    for (int i = tid; i < cnt; i += THREADS) sW[KOFS_[kidx] + i] = wg[i];
  }
  __syncthreads();
  conv_k<L, 1>(sX, sW + 0,    sF, lane, fpair, S * 80 + 0);
  conv_k<L, 3>(sX, sW + 320,  sF, lane, fpair, S * 80 + 16);
  conv_k<L, 5>(sX, sW + 1280, sF, lane, fpair, S * 80 + 32);
  conv_k<L, 7>(sX, sW + 2880, sF, lane, fpair, S * 80 + 48);
  conv_k<L, 9>(sX, sW + 5120, sF, lane, fpair, S * 80 + 64);
  __syncthreads();   // sX/sW reused by next sequence
}

__global__ __launch_bounds__(THREADS, 1) void cnn_fused_kernel(Params p) {
  extern __shared__ float smem[];
  float* sW = smem + SW_OFS;
  float* sX = smem + SX_OFS;
  float* sF = smem + SF_OFS;
  float* sH = smem + SH_OFS;
  const int tid   = threadIdx.x;
  const int lane  = tid & 31;     // batch element within tile
  const int fpair = tid >> 5;     // warp id = filter pair / GEMV row group
  const int bbase = blockIdx.x * TB;

  do_seq<12, 0>(p, sW, sX, sF, tid, lane, fpair, bbase);  // pep
  do_seq< 7, 1>(p, sW, sX, sF, tid, lane, fpair, bbase);  // a1
  do_seq< 8, 2>(p, sW, sX, sF, tid, lane, fpair, bbase);  // a2
  do_seq<16, 3>(p, sW, sX, sF, tid, lane, fpair, bbase);  // a3
  do_seq< 6, 4>(p, sW, sX, sF, tid, lane, fpair, bbase);  // b1
  do_seq< 7, 5>(p, sW, sX, sF, tid, lane, fpair, bbase);  // b2
  do_seq<18, 6>(p, sW, sX, sF, tid, lane, fpair, bbase);  // b3

  // --- MLP: h = sigmoid(feats @ W1^T + b1) ---
  {
    const int g = fpair;                 // rows j = g*8 .. g*8+7
    float acc[8];
    #pragma unroll
    for (int jj = 0; jj < 8; ++jj) acc[jj] = p.lin1_b[g * 8 + jj];
    const float* fr = sF + lane * FSTRIDE;
    const float* w1 = p.lin1_w + (size_t)(g * 8) * FEAT;
    #pragma unroll 4
    for (int i = 0; i < FEAT; ++i) {
      const float fv = fr[i];
      #pragma unroll
      for (int jj = 0; jj < 8; ++jj)
        acc[jj] = fmaf(fv, __ldg(w1 + jj * FEAT + i), acc[jj]);
    }
    #pragma unroll
    for (int jj = 0; jj < 8; ++jj)
      sH[lane * HSTRIDE + g * 8 + jj] = 1.f / (1.f + expf(-acc[jj]));
  }
  __syncthreads();

  // --- out = h @ W2^T + b2 ---
  if (tid < TB) {
    const int bg = bbase + tid;
    if (bg < p.B) {
      float o = p.lin2_b[0];
      #pragma unroll
      for (int j = 0; j < 64; ++j)
        o = fmaf(sH[tid * HSTRIDE + j], __ldg(p.lin2_w + j), o);
      p.out[bg] = o;
    }
  }
}

} // namespace

extern "C" void kernel_launch(void* const* d_in, const int* in_sizes, int n_in,
                              void* d_out, int out_size) {
  Params p;
  for (int i = 0; i < 7; ++i) p.seq[i] = (const float*)d_in[i];
  for (int j = 0; j < 5; ++j) p.Wk[j] = (const float*)d_in[7 + j];
  p.lin1_w = (const float*)d_in[12];
  p.lin1_b = (const float*)d_in[13];
  p.lin2_w = (const float*)d_in[14];
  p.lin2_b = (const float*)d_in[15];
  p.out = (float*)d_out;
  p.B   = out_size;

  cudaFuncSetAttribute(cnn_fused_kernel,
                       cudaFuncAttributeMaxDynamicSharedMemorySize, SMEM_BYTES);

  const int grid = (p.B + TB - 1) / TB;
  cnn_fused_kernel<<<grid, THREADS, SMEM_BYTES>>>(p);
}

// round 2
// speedup vs baseline: 1.0956x; 1.0956x over previous
#include <cuda_runtime.h>
#include <math.h>

namespace {

constexpr int EMBED   = 20;
constexpr int TB      = 32;    // batch elems per CTA
constexpr int THREADS = 256;   // 8 warps = 8 filter-pairs
constexpr int FEAT    = 560;
constexpr int BATCH_MAX = 16384;

// ---------------- packed f32x2 helpers (Blackwell FFMA2) ----------------
__device__ __forceinline__ unsigned long long pack2(float a, float b) {
  unsigned long long r;
  asm("mov.b64 %0, {%1, %2};" : "=l"(r) : "f"(a), "f"(b));
  return r;
}
__device__ __forceinline__ void unpack2(unsigned long long v, float& a, float& b) {
  asm("mov.b64 {%0, %1}, %2;" : "=f"(a), "=f"(b) : "l"(v));
}
__device__ __forceinline__ unsigned long long fma2(unsigned long long a,
                                                   unsigned long long b,
                                                   unsigned long long c) {
  unsigned long long d;
  asm("fma.rn.f32x2 %0, %1, %2, %3;" : "=l"(d) : "l"(a), "l"(b), "l"(c));
  return d;
}

// ---------------- feature scratch: transposed [FEAT][B] ----------------
__device__ float g_feat[FEAT * BATCH_MAX];

struct ConvParams {
  const float* seq[7];
  const float* Wk[5];
  int B;
};
struct MlpParams {
  const float* lin1_w;
  const float* lin1_b;
  const float* lin2_w;
  const float* lin2_b;
  float* out;
  int B;
};

// smem for conv kernel: sX padded [20*L][33] + packed weight pairs (4000 float2)
constexpr int SXP_STRIDE = 33;
constexpr int SX_MAXF    = EMBED * 18 * SXP_STRIDE;   // 11880 floats
constexpr int SWP_F2     = 4000;                      // float2 count (all 5 ksizes)
constexpr int CONV_SMEM_BYTES = SX_MAXF * 4 + SWP_F2 * 8;  // 47520+32000 = 79520

__constant__ int c_kofs2[5] = {0, 160, 640, 1440, 2560}; // float2 offsets per ksize

// one (seq,k) conv + relu + gmax for the thread's 2 filters, packed f32x2
template<int L, int K>
__device__ __forceinline__ void conv_k(const float* __restrict__ sX,
                                       const float2* __restrict__ sWp,
                                       int lane, int fpair,
                                       int featBase, int bg, int B) {
  constexpr int PAD = (K - 1) / 2;
  unsigned long long acc[L];
  #pragma unroll
  for (int t = 0; t < L; ++t) acc[t] = 0ULL;

  #pragma unroll 2
  for (int c = 0; c < EMBED; ++c) {
    unsigned long long xx[L];
    #pragma unroll
    for (int l = 0; l < L; ++l) {
      const float x = sX[(c * L + l) * SXP_STRIDE + lane];
      xx[l] = pack2(x, x);
    }
    unsigned long long wp[K];
    #pragma unroll
    for (int j = 0; j < K; ++j) {
      const float2 w = sWp[(fpair * EMBED + c) * K + j];  // broadcast, LDS.64
      wp[j] = pack2(w.x, w.y);
    }
    #pragma unroll
    for (int t = 0; t < L; ++t) {
      #pragma unroll
      for (int j = 0; j < K; ++j) {
        const int xi = t + j - PAD;            // compile-time predicate
        if (xi >= 0 && xi < L) acc[t] = fma2(xx[xi], wp[j], acc[t]);
      }
    }
  }
  float m0 = 0.f, m1 = 0.f;                    // relu+gmax = max(0, max_t)
  #pragma unroll
  for (int t = 0; t < L; ++t) {
    float a, b; unpack2(acc[t], a, b);
    m0 = fmaxf(m0, a); m1 = fmaxf(m1, b);
  }
  g_feat[(size_t)(featBase + 2 * fpair)     * B + bg] = m0;
  g_feat[(size_t)(featBase + 2 * fpair + 1) * B + bg] = m1;
}

template<int L, int S>
__device__ __forceinline__ void do_seq(const ConvParams& p, float* sX, float2* sWp,
                                       int tid, int lane, int fpair, int bbase) {
  // stage x tile -> [c*L+l][lane], fold the /5
  const float* xg = p.seq[S];
  constexpr int CL = EMBED * L;
  for (int idx = tid; idx < CL * TB; idx += THREADS) {
    const int b   = idx / CL;
    const int rem = idx - b * CL;
    int bg = bbase + b;
    if (bg >= p.B) bg = p.B - 1;
    sX[rem * SXP_STRIDE + b] = xg[(size_t)bg * CL + rem] * 0.2f;
  }
  // stage packed weight pairs for all 5 ksizes of this sequence
  constexpr int KS_[5] = {1, 3, 5, 7, 9};
  #pragma unroll
  for (int kidx = 0; kidx < 5; ++kidx) {
    const int k    = KS_[kidx];
    const int cnt2 = 8 * EMBED * k;                 // float2 count
    const float* wg = p.Wk[kidx] + (size_t)S * (16 * EMBED * k);
    for (int i = tid; i < cnt2; i += THREADS) {
      const int fp  = i / (EMBED * k);
      const int rem = i - fp * (EMBED * k);         // c*k + j
      sWp[c_kofs2[kidx] + i] =
          make_float2(wg[(2 * fp) * EMBED * k + rem],
                      wg[(2 * fp + 1) * EMBED * k + rem]);
    }
  }
  __syncthreads();
  const int bg = min(bbase + lane, p.B - 1);
  conv_k<L, 1>(sX, sWp + 0,    lane, fpair, S * 80 + 0,  bg, p.B);
  conv_k<L, 3>(sX, sWp + 160,  lane, fpair, S * 80 + 16, bg, p.B);
  conv_k<L, 5>(sX, sWp + 640,  lane, fpair, S * 80 + 32, bg, p.B);
  conv_k<L, 7>(sX, sWp + 1440, lane, fpair, S * 80 + 48, bg, p.B);
  conv_k<L, 9>(sX, sWp + 2560, lane, fpair, S * 80 + 64, bg, p.B);
}

__global__ __launch_bounds__(THREADS, 2) void conv_kernel(ConvParams p) {
  extern __shared__ float smem[];
  float*  sX  = smem;
  float2* sWp = (float2*)(smem + SX_MAXF);
  const int tid   = threadIdx.x;
  const int lane  = tid & 31;
  const int fpair = tid >> 5;
  const int bbase = blockIdx.x * TB;
  switch (blockIdx.y) {
    case 0: do_seq<12, 0>(p, sX, sWp, tid, lane, fpair, bbase); break;
    case 1: do_seq< 7, 1>(p, sX, sWp, tid, lane, fpair, bbase); break;
    case 2: do_seq< 8, 2>(p, sX, sWp, tid, lane, fpair, bbase); break;
    case 3: do_seq<16, 3>(p, sX, sWp, tid, lane, fpair, bbase); break;
    case 4: do_seq< 6, 4>(p, sX, sWp, tid, lane, fpair, bbase); break;
    case 5: do_seq< 7, 5>(p, sX, sWp, tid, lane, fpair, bbase); break;
    case 6: do_seq<18, 6>(p, sX, sWp, tid, lane, fpair, bbase); break;
  }
}

// ---------------- MLP kernel: h = sigmoid(F@W1^T+b1); out = h@W2^T+b2 ----
constexpr int HSTRIDE = 65;
constexpr int W1P_F2  = FEAT * 32;                        // 17920 float2
constexpr int MLP_SMEM_BYTES = W1P_F2 * 8 + TB * HSTRIDE * 4;  // 143360+8320

__global__ __launch_bounds__(THREADS, 1) void mlp_kernel(MlpParams p) {
  extern __shared__ float smem[];
  float2* sW1p = (float2*)smem;
  float*  sH   = smem + W1P_F2 * 2;
  const int tid   = threadIdx.x;
  const int lane  = tid & 31;
  const int g     = tid >> 5;
  const int bbase = blockIdx.x * TB;

  // stage packed W1: sW1p[i*32 + g*4 + p] = (W1[g*8+2p][i], W1[g*8+2p+1][i])
  for (int idx = tid; idx < W1P_F2; idx += THREADS) {
    const int i   = idx >> 5;
    const int col = idx & 31;
    const int gg  = col >> 2;
    const int pp  = col & 3;
    const int j0  = gg * 8 + 2 * pp;
    sW1p[idx] = make_float2(p.lin1_w[(size_t)j0 * FEAT + i],
                            p.lin1_w[(size_t)(j0 + 1) * FEAT + i]);
  }
  __syncthreads();

  const int bg = min(bbase + lane, p.B - 1);
  unsigned long long acc[4];
  #pragma unroll
  for (int pp = 0; pp < 4; ++pp)
    acc[pp] = pack2(p.lin1_b[g * 8 + 2 * pp], p.lin1_b[g * 8 + 2 * pp + 1]);

  #pragma unroll 4
  for (int i = 0; i < FEAT; ++i) {
    const float f = g_feat[(size_t)i * p.B + bg];   // coalesced
    const unsigned long long ff = pack2(f, f);
    #pragma unroll
    for (int pp = 0; pp < 4; ++pp) {
      const float2 w = sW1p[i * 32 + g * 4 + pp];
      acc[pp] = fma2(ff, pack2(w.x, w.y), acc[pp]);
    }
  }
  #pragma unroll
  for (int pp = 0; pp < 4; ++pp) {
    float a, b; unpack2(acc[pp], a, b);
    sH[lane * HSTRIDE + g * 8 + 2 * pp]     = 1.f / (1.f + expf(-a));
    sH[lane * HSTRIDE + g * 8 + 2 * pp + 1] = 1.f / (1.f + expf(-b));
  }
  __syncthreads();

  if (tid < TB) {
    const int bgo = bbase + tid;
    if (bgo < p.B) {
      float o = p.lin2_b[0];
      #pragma unroll
      for (int j = 0; j < 64; ++j)
        o = fmaf(sH[tid * HSTRIDE + j], __ldg(p.lin2_w + j), o);
      p.out[bgo] = o;
    }
  }
}

} // namespace

extern "C" void kernel_launch(void* const* d_in, const int* in_sizes, int n_in,
                              void* d_out, int out_size) {
  ConvParams cp;
  for (int i = 0; i < 7; ++i) cp.seq[i] = (const float*)d_in[i];
  for (int j = 0; j < 5; ++j) cp.Wk[j] = (const float*)d_in[7 + j];
  cp.B = out_size;

  MlpParams mp;
  mp.lin1_w = (const float*)d_in[12];
  mp.lin1_b = (const float*)d_in[13];
  mp.lin2_w = (const float*)d_in[14];
  mp.lin2_b = (const float*)d_in[15];
  mp.out = (float*)d_out;
  mp.B   = out_size;

  static bool attr_set = false;
  if (!attr_set) {
    cudaFuncSetAttribute(conv_kernel,
                         cudaFuncAttributeMaxDynamicSharedMemorySize, CONV_SMEM_BYTES);
    cudaFuncSetAttribute(mlp_kernel,
                         cudaFuncAttributeMaxDynamicSharedMemorySize, MLP_SMEM_BYTES);
    attr_set = true;
  }

  const int tiles = (cp.B + TB - 1) / TB;
  dim3 cgrid(tiles, 7);
  conv_kernel<<<cgrid, THREADS, CONV_SMEM_BYTES>>>(cp);
  mlp_kernel<<<tiles, THREADS, MLP_SMEM_BYTES>>>(mp);
}

// round 3
// speedup vs baseline: 1.1293x; 1.0307x over previous
#include <cuda_runtime.h>
#include <math.h>

namespace {

constexpr int EMBED     = 20;
constexpr int THREADS   = 256;
constexpr int FEAT      = 560;
constexpr int BATCH_MAX = 16384;

typedef unsigned long long ull;

// ---------------- packed f32x2 helpers (Blackwell FFMA2) ----------------
__device__ __forceinline__ ull pack2(float a, float b) {
  ull r;
  asm("mov.b64 %0, {%1, %2};" : "=l"(r) : "f"(a), "f"(b));
  return r;
}
__device__ __forceinline__ void unpack2(ull v, float& a, float& b) {
  asm("mov.b64 {%0, %1}, %2;" : "=f"(a), "=f"(b) : "l"(v));
}
__device__ __forceinline__ ull fma2(ull a, ull b, ull c) {
  ull d;
  asm("fma.rn.f32x2 %0, %1, %2, %3;" : "=l"(d) : "l"(a), "l"(b), "l"(c));
  return d;
}

// ---------------- global scratch ----------------
__device__ float  g_feat[FEAT * BATCH_MAX];     // transposed [feat][B]
__device__ float2 g_w1p[FEAT * 32];             // [i][col] = (W1[2c][i], W1[2c+1][i])

struct ConvParams {
  const float* seq[7];
  const float* Wk[5];
  int B;
};
struct MlpParams {
  const float* lin1_w;
  const float* lin1_b;
  const float* lin2_w;
  const float* lin2_b;
  float* out;
  int B;
};

// smem: weights scalar [f][c][k] for all 5 ksizes (8000 fl) + x region
constexpr int SW_FLOATS   = 8000;
constexpr int SX_BYTES    = EMBED * 12 * 33 * 8;     // 63360 (pep paired, max)
constexpr int CONV_SMEM_BYTES = SW_FLOATS * 4 + SX_BYTES;  // 95360

// scalar weight offsets per ksize within sW
__device__ __forceinline__ constexpr int kofs(int kidx) {
  constexpr int o[5] = {0, 320, 1280, 2880, 5120};
  return o[kidx];
}

// ---- paired conv: thread = (batch pair lane, warp->2 filters looped) ----
template<int L, int K>
__device__ __forceinline__ void pconv(const float2* __restrict__ sX2,
                                      const float* __restrict__ sWk,
                                      int lane, int w, int featBase,
                                      int bg0, int bg1, int B) {
  constexpr int PAD = (K - 1) / 2;
  #pragma unroll
  for (int fi = 0; fi < 2; ++fi) {
    const int f = 2 * w + fi;
    ull acc[L];
    #pragma unroll
    for (int t = 0; t < L; ++t) acc[t] = 0ULL;
    #pragma unroll 2
    for (int c = 0; c < EMBED; ++c) {
      ull xx[L];
      #pragma unroll
      for (int l = 0; l < L; ++l) {
        const float2 v = sX2[(c * L + l) * 33 + lane];   // LDS.64
        xx[l] = pack2(v.x, v.y);
      }
      ull wt[K];
      #pragma unroll
      for (int j = 0; j < K; ++j) {
        const float wv = sWk[(f * EMBED + c) * K + j];   // uniform broadcast
        wt[j] = pack2(wv, wv);
      }
      #pragma unroll
      for (int t = 0; t < L; ++t) {
        #pragma unroll
        for (int j = 0; j < K; ++j) {
          const int xi = t + j - PAD;                    // compile-time pred
          if (xi >= 0 && xi < L) acc[t] = fma2(xx[xi], wt[j], acc[t]);
        }
      }
    }
    float m0 = 0.f, m1 = 0.f;                            // relu+gmax
    #pragma unroll
    for (int t = 0; t < L; ++t) {
      float a, b; unpack2(acc[t], a, b);
      m0 = fmaxf(m0, a); m1 = fmaxf(m1, b);
    }
    g_feat[(size_t)(featBase + f) * B + bg0] = m0;
    g_feat[(size_t)(featBase + f) * B + bg1] = m1;
  }
}

// ---- unpaired conv (large L): x duplicated into both halves ----
template<int L, int K>
__device__ __forceinline__ void uconv(const float* __restrict__ sX,
                                      const float* __restrict__ sWk,
                                      int lane, int w, int featBase,
                                      int bg, int B) {
  constexpr int PAD = (K - 1) / 2;
  #pragma unroll
  for (int fi = 0; fi < 2; ++fi) {
    const int f = 2 * w + fi;
    ull acc[L];
    #pragma unroll
    for (int t = 0; t < L; ++t) acc[t] = 0ULL;
    #pragma unroll 2
    for (int c = 0; c < EMBED; ++c) {
      ull xx[L];
      #pragma unroll
      for (int l = 0; l < L; ++l) {
        const float v = sX[(c * L + l) * 33 + lane];
        xx[l] = pack2(v, v);
      }
      ull wt[K];
      #pragma unroll
      for (int j = 0; j < K; ++j) {
        const float wv = sWk[(f * EMBED + c) * K + j];
        wt[j] = pack2(wv, wv);
      }
      #pragma unroll
      for (int t = 0; t < L; ++t) {
        #pragma unroll
        for (int j = 0; j < K; ++j) {
          const int xi = t + j - PAD;
          if (xi >= 0 && xi < L) acc[t] = fma2(xx[xi], wt[j], acc[t]);
        }
      }
    }
    float m0 = 0.f, m1 = 0.f;
    #pragma unroll
    for (int t = 0; t < L; ++t) {
      float a, b; unpack2(acc[t], a, b);
      m0 = fmaxf(m0, fmaxf(a, b));   // a==b path; keep both for safety
      m1 = m0;
    }
    // note: duplicated halves hold the SAME batch elem; write once
    g_feat[(size_t)(featBase + f) * B + bg] = m0;
    (void)m1;
  }
}

__device__ __forceinline__ void stage_weights(const ConvParams& p, float* sW,
                                              int S, int tid) {
  constexpr int KS_[5] = {1, 3, 5, 7, 9};
  #pragma unroll
  for (int kidx = 0; kidx < 5; ++kidx) {
    const int k   = KS_[kidx];
    const int cnt = 16 * EMBED * k;
    const float* wg = p.Wk[kidx] + (size_t)S * cnt;
    for (int i = tid; i < cnt; i += THREADS) sW[kofs(kidx) + i] = wg[i];
  }
}

template<int L, int S>
__device__ void do_seq_paired(const ConvParams& p, float* sW, float2* sX2,
                              int tid, int lane, int w, int bbase64) {
  const float* xg = p.seq[S];
  constexpr int CL = EMBED * L;
  for (int idx = tid; idx < CL * 32; idx += THREADS) {
    const int bp  = idx / CL;
    const int rem = idx - bp * CL;
    int b0 = bbase64 + bp;
    if (b0 + 32 >= p.B) b0 = p.B - 33 >= 0 ? min(b0, p.B - 33) : 0;
    sX2[rem * 33 + bp] = make_float2(xg[(size_t)b0 * CL + rem] * 0.2f,
                                     xg[(size_t)(b0 + 32) * CL + rem] * 0.2f);
  }
  stage_weights(p, sW, S, tid);
  __syncthreads();
  const int bg0 = min(bbase64 + lane, p.B - 1);
  const int bg1 = min(bg0 + 32, p.B - 1);
  pconv<L, 1>(sX2, sW + 0,    lane, w, S * 80 + 0,  bg0, bg1, p.B);
  pconv<L, 3>(sX2, sW + 320,  lane, w, S * 80 + 16, bg0, bg1, p.B);
  pconv<L, 5>(sX2, sW + 1280, lane, w, S * 80 + 32, bg0, bg1, p.B);
  pconv<L, 7>(sX2, sW + 2880, lane, w, S * 80 + 48, bg0, bg1, p.B);
  pconv<L, 9>(sX2, sW + 5120, lane, w, S * 80 + 64, bg0, bg1, p.B);
}

template<int L, int S>
__device__ void do_seq_unpaired2(const ConvParams& p, float* sW, float* sX,
                                 int tid, int lane, int w, int bbase64) {
  const float* xg = p.seq[S];
  constexpr int CL = EMBED * L;
  stage_weights(p, sW, S, tid);
  #pragma unroll
  for (int half = 0; half < 2; ++half) {
    const int bbase = bbase64 + half * 32;
    for (int idx = tid; idx < CL * 32; idx += THREADS) {
      const int b   = idx / CL;
      const int rem = idx - b * CL;
      int bg = min(bbase + b, p.B - 1);
      sX[rem * 33 + b] = xg[(size_t)bg * CL + rem] * 0.2f;
    }
    __syncthreads();
    const int bg = min(bbase + lane, p.B - 1);
    uconv<L, 1>(sX, sW + 0,    lane, w, S * 80 + 0,  bg, p.B);
    uconv<L, 3>(sX, sW + 320,  lane, w, S * 80 + 16, bg, p.B);
    uconv<L, 5>(sX, sW + 1280, lane, w, S * 80 + 32, bg, p.B);
    uconv<L, 7>(sX, sW + 2880, lane, w, S * 80 + 48, bg, p.B);
    uconv<L, 9>(sX, sW + 5120, lane, w, S * 80 + 64, bg, p.B);
    if (half == 0) __syncthreads();   // protect sX before restage
  }
}

__global__ __launch_bounds__(THREADS, 2) void conv_kernel(ConvParams p) {
  extern __shared__ float smem[];
  float*  sW  = smem;
  float*  sX  = smem + SW_FLOATS;
  float2* sX2 = (float2*)(smem + SW_FLOATS);
  const int tid  = threadIdx.x;
  const int lane = tid & 31;
  const int w    = tid >> 5;
  const int bbase64 = blockIdx.x * 64;
  switch (blockIdx.y) {
    case 0: do_seq_paired  <12, 0>(p, sW, sX2, tid, lane, w, bbase64); break;
    case 1: do_seq_paired  < 7, 1>(p, sW, sX2, tid, lane, w, bbase64); break;
    case 2: do_seq_paired  < 8, 2>(p, sW, sX2, tid, lane, w, bbase64); break;
    case 3: do_seq_unpaired2<16, 3>(p, sW, sX,  tid, lane, w, bbase64); break;
    case 4: do_seq_paired  < 6, 4>(p, sW, sX2, tid, lane, w, bbase64); break;
    case 5: do_seq_paired  < 7, 5>(p, sW, sX2, tid, lane, w, bbase64); break;
    case 6: do_seq_unpaired2<18, 6>(p, sW, sX,  tid, lane, w, bbase64); break;
  }
}

// ---------------- W1 pre-pack: g_w1p[i*32+col] = (W1[2col][i], W1[2col+1][i])
__global__ void prep_w1_kernel(const float* __restrict__ w1) {
  const int idx = blockIdx.x * 256 + threadIdx.x;
  if (idx < FEAT * 32) {
    const int i   = idx >> 5;
    const int col = idx & 31;
    g_w1p[idx] = make_float2(w1[(size_t)(2 * col) * FEAT + i],
                             w1[(size_t)(2 * col + 1) * FEAT + i]);
  }
}

// ---------------- MLP: 64 batch per CTA, 2 batch/thread, f32x2 ----------
constexpr int MLP_SMEM_BYTES = 64 * 65 * 4;

__global__ __launch_bounds__(THREADS) void mlp_kernel(MlpParams p) {
  extern __shared__ float sH[];   // [64 batch][65]
  const int tid   = threadIdx.x;
  const int lane  = tid & 31;
  const int g     = tid >> 5;            // warp -> rows 8g..8g+7 (cols g*4..g*4+3)
  const int bbase = blockIdx.x * 64;
  const int b0 = min(bbase + lane, p.B - 1);
  const int b1 = min(b0 + 32, p.B - 1);

  ull acc0[4], acc1[4];
  #pragma unroll
  for (int pp = 0; pp < 4; ++pp) {
    const ull bia = pack2(p.lin1_b[g * 8 + 2 * pp], p.lin1_b[g * 8 + 2 * pp + 1]);
    acc0[pp] = bia; acc1[pp] = bia;
  }

  const float4* wbase = (const float4*)(g_w1p);  // 2 float2 per float4
  #pragma unroll 4
  for (int i = 0; i < FEAT; ++i) {
    const float f0 = g_feat[(size_t)i * p.B + b0];
    const float f1 = g_feat[(size_t)i * p.B + b1];
    const ull ff0 = pack2(f0, f0);
    const ull ff1 = pack2(f1, f1);
    const float4 wa = wbase[i * 16 + g * 2];       // cols g*4, g*4+1
    const float4 wb = wbase[i * 16 + g * 2 + 1];   // cols g*4+2, g*4+3
    const ull w0 = pack2(wa.x, wa.y);
    const ull w1v = pack2(wa.z, wa.w);
    const ull w2 = pack2(wb.x, wb.y);
    const ull w3 = pack2(wb.z, wb.w);
    acc0[0] = fma2(ff0, w0, acc0[0]);  acc1[0] = fma2(ff1, w0, acc1[0]);
    acc0[1] = fma2(ff0, w1v, acc0[1]); acc1[1] = fma2(ff1, w1v, acc1[1]);
    acc0[2] = fma2(ff0, w2, acc0[2]);  acc1[2] = fma2(ff1, w2, acc1[2]);
    acc0[3] = fma2(ff0, w3, acc0[3]);  acc1[3] = fma2(ff1, w3, acc1[3]);
  }
  #pragma unroll
  for (int pp = 0; pp < 4; ++pp) {
    float a, b;
    unpack2(acc0[pp], a, b);
    sH[lane * 65 + g * 8 + 2 * pp]     = 1.f / (1.f + __expf(-a));
    sH[lane * 65 + g * 8 + 2 * pp + 1] = 1.f / (1.f + __expf(-b));
    unpack2(acc1[pp], a, b);
    sH[(lane + 32) * 65 + g * 8 + 2 * pp]     = 1.f / (1.f + __expf(-a));
    sH[(lane + 32) * 65 + g * 8 + 2 * pp + 1] = 1.f / (1.f + __expf(-b));
  }
  __syncthreads();

  if (tid < 64) {
    const int bgo = bbase + tid;
    if (bgo < p.B) {
      float o = p.lin2_b[0];
      #pragma unroll
      for (int j = 0; j < 64; ++j)
        o = fmaf(sH[tid * 65 + j], __ldg(p.lin2_w + j), o);
      p.out[bgo] = o;
    }
  }
}

} // namespace

extern "C" void kernel_launch(void* const* d_in, const int* in_sizes, int n_in,
                              void* d_out, int out_size) {
  ConvParams cp;
  for (int i = 0; i < 7; ++i) cp.seq[i] = (const float*)d_in[i];
  for (int j = 0; j < 5; ++j) cp.Wk[j] = (const float*)d_in[7 + j];
  cp.B = out_size;

  MlpParams mp;
  mp.lin1_w = (const float*)d_in[12];
  mp.lin1_b = (const float*)d_in[13];
  mp.lin2_w = (const float*)d_in[14];
  mp.lin2_b = (const float*)d_in[15];
  mp.out = (float*)d_out;
  mp.B   = out_size;

  static bool attr_set = false;
  if (!attr_set) {
    cudaFuncSetAttribute(conv_kernel,
                         cudaFuncAttributeMaxDynamicSharedMemorySize, CONV_SMEM_BYTES);
    attr_set = true;
  }

  const int tiles64 = (cp.B + 63) / 64;
  prep_w1_kernel<<<(FEAT * 32 + 255) / 256, 256>>>(mp.lin1_w);
  dim3 cgrid(tiles64, 7);
  conv_kernel<<<cgrid, THREADS, CONV_SMEM_BYTES>>>(cp);
  mlp_kernel<<<tiles64, THREADS, MLP_SMEM_BYTES>>>(mp);
}

// round 4
// speedup vs baseline: 1.2430x; 1.1007x over previous
#include <cuda_runtime.h>
#include <math.h>

namespace {

constexpr int EMBED     = 20;
constexpr int THREADS   = 256;
constexpr int FEAT      = 560;
constexpr int BATCH_MAX = 16384;

typedef unsigned long long ull;

// ---------------- packed f32x2 helpers (Blackwell FFMA2) ----------------
__device__ __forceinline__ ull pack2(float a, float b) {
  ull r;
  asm("mov.b64 %0, {%1, %2};" : "=l"(r) : "f"(a), "f"(b));
  return r;
}
__device__ __forceinline__ void unpack2(ull v, float& a, float& b) {
  asm("mov.b64 {%0, %1}, %2;" : "=f"(a), "=f"(b) : "l"(v));
}
__device__ __forceinline__ ull fma2(ull a, ull b, ull c) {
  ull d;
  asm("fma.rn.f32x2 %0, %1, %2, %3;" : "=l"(d) : "l"(a), "l"(b), "l"(c));
  return d;
}

// ---------------- global scratch ----------------
__device__ float  g_feat[FEAT * BATCH_MAX];   // transposed [feat][B]
__device__ float2 g_w1p[FEAT * 32];           // [i][col]=(W1[2c][i],W1[2c+1][i])

struct ConvParams {
  const float* seq[7];
  const float* Wk[5];
  int B;
};
struct MlpParams {
  const float* lin1_w;
  const float* lin1_b;
  const float* lin2_w;
  const float* lin2_b;
  float* out;
  int B;
};

// smem: packed weight pairs (4000 float2 = 32000B) + x region
// dup path (L<=12):  20*12*33 float2 = 63360B  -> total 95360
// long path (L<=18): 20*18*33 float  = 47520B  -> total 79520
constexpr int SWP_F2 = 4000;
constexpr int CONV_SMEM_BYTES = SWP_F2 * 8 + EMBED * 12 * 33 * 8;  // 95360

// ---- short-L conv: x pre-duplicated (x,x), weights pre-paired (w0,w1) ----
// thread = (lane=batch, warp=filter-pair); zero pack-movs in the hot loop.
template<int L, int K>
__device__ __forceinline__ void conv_dup(const ull* __restrict__ sXu,
                                         const ull* __restrict__ sWu,
                                         int lane, int w, int featBase,
                                         int bg, int B) {
  constexpr int PAD = (K - 1) / 2;
  ull acc[L];
  #pragma unroll
  for (int t = 0; t < L; ++t) acc[t] = 0ULL;
  for (int c = 0; c < EMBED; ++c) {
    ull xx[L];
    #pragma unroll
    for (int l = 0; l < L; ++l) xx[l] = sXu[(c * L + l) * 33 + lane];  // LDS.64
    ull wt[K];
    #pragma unroll
    for (int j = 0; j < K; ++j) wt[j] = sWu[(w * EMBED + c) * K + j];  // bcast
    #pragma unroll
    for (int t = 0; t < L; ++t) {
      #pragma unroll
      for (int j = 0; j < K; ++j) {
        const int xi = t + j - PAD;            // compile-time predicate
        if (xi >= 0 && xi < L) acc[t] = fma2(xx[xi], wt[j], acc[t]);
      }
    }
  }
  float m0 = 0.f, m1 = 0.f;                    // relu + global max
  #pragma unroll
  for (int t = 0; t < L; ++t) {
    float a, b; unpack2(acc[t], a, b);
    m0 = fmaxf(m0, a); m1 = fmaxf(m1, b);
  }
  g_feat[(size_t)(featBase + 2 * w)     * B + bg] = m0;
  g_feat[(size_t)(featBase + 2 * w + 1) * B + bg] = m1;
}

// ---- long-L conv: t-tiled (halves register arrays; avoids spills) ----
template<int L, int K, int T0, int T1>
__device__ __forceinline__ void conv_tile(const float* __restrict__ sX,
                                          const ull* __restrict__ sWu,
                                          int lane, int w, float& m0, float& m1) {
  constexpr int PAD = (K - 1) / 2;
  constexpr int XLO = (T0 - PAD > 0) ? (T0 - PAD) : 0;
  constexpr int XHI = (T1 + PAD < L) ? (T1 + PAD) : L;   // exclusive
  constexpr int NT  = T1 - T0;
  ull acc[NT];
  #pragma unroll
  for (int t = 0; t < NT; ++t) acc[t] = 0ULL;
  for (int c = 0; c < EMBED; ++c) {
    ull xx[XHI - XLO];
    #pragma unroll
    for (int l = 0; l < XHI - XLO; ++l) {
      const float v = sX[(c * L + XLO + l) * 33 + lane];
      xx[l] = pack2(v, v);
    }
    ull wt[K];
    #pragma unroll
    for (int j = 0; j < K; ++j) wt[j] = sWu[(w * EMBED + c) * K + j];
    #pragma unroll
    for (int t = T0; t < T1; ++t) {
      #pragma unroll
      for (int j = 0; j < K; ++j) {
        const int xi = t + j - PAD;
        if (xi >= 0 && xi < L) acc[t - T0] = fma2(xx[xi - XLO], wt[j], acc[t - T0]);
      }
    }
  }
  #pragma unroll
  for (int t = 0; t < NT; ++t) {
    float a, b; unpack2(acc[t], a, b);
    m0 = fmaxf(m0, a); m1 = fmaxf(m1, b);
  }
}

template<int L, int K>
__device__ __forceinline__ void conv_long(const float* __restrict__ sX,
                                          const ull* __restrict__ sWu,
                                          int lane, int w, int featBase,
                                          int bg, int B) {
  float m0 = 0.f, m1 = 0.f;
  conv_tile<L, K, 0, L / 2>(sX, sWu, lane, w, m0, m1);
  conv_tile<L, K, L / 2, L>(sX, sWu, lane, w, m0, m1);
  g_feat[(size_t)(featBase + 2 * w)     * B + bg] = m0;
  g_feat[(size_t)(featBase + 2 * w + 1) * B + bg] = m1;
}

// stage packed weight pairs for all 5 ksizes of sequence S
__device__ __forceinline__ void stage_wpairs(const ConvParams& p, float2* sWp,
                                             int S, int tid) {
  constexpr int KS_[5]    = {1, 3, 5, 7, 9};
  constexpr int KOFS2_[5] = {0, 160, 640, 1440, 2560};
  #pragma unroll
  for (int kidx = 0; kidx < 5; ++kidx) {
    const int k    = KS_[kidx];
    const int cnt2 = 8 * EMBED * k;
    const float* wg = p.Wk[kidx] + (size_t)S * (16 * EMBED * k);
    for (int i = tid; i < cnt2; i += THREADS) {
      const int fp  = i / (EMBED * k);
      const int rem = i - fp * (EMBED * k);
      sWp[KOFS2_[kidx] + i] = make_float2(wg[(2 * fp) * EMBED * k + rem],
                                          wg[(2 * fp + 1) * EMBED * k + rem]);
    }
  }
}

template<int L, int S>
__device__ void do_seq_dup(const ConvParams& p, float2* sWp, float2* sX2,
                           int tid, int lane, int w, int bbase) {
  const float* xg = p.seq[S];
  constexpr int CL = EMBED * L;
  for (int idx = tid; idx < CL * 32; idx += THREADS) {
    const int b   = idx / CL;
    const int rem = idx - b * CL;
    const int bg  = min(bbase + b, p.B - 1);
    const float v = xg[(size_t)bg * CL + rem] * 0.2f;
    sX2[rem * 33 + b] = make_float2(v, v);
  }
  stage_wpairs(p, sWp, S, tid);
  __syncthreads();
  const ull* sXu = (const ull*)sX2;
  const ull* sWu = (const ull*)sWp;
  const int bg = min(bbase + lane, p.B - 1);
  conv_dup<L, 1>(sXu, sWu + 0,    lane, w, S * 80 + 0,  bg, p.B);
  conv_dup<L, 3>(sXu, sWu + 160,  lane, w, S * 80 + 16, bg, p.B);
  conv_dup<L, 5>(sXu, sWu + 640,  lane, w, S * 80 + 32, bg, p.B);
  conv_dup<L, 7>(sXu, sWu + 1440, lane, w, S * 80 + 48, bg, p.B);
  conv_dup<L, 9>(sXu, sWu + 2560, lane, w, S * 80 + 64, bg, p.B);
}

template<int L, int S>
__device__ void do_seq_long(const ConvParams& p, float2* sWp, float* sX,
                            int tid, int lane, int w, int bbase) {
  const float* xg = p.seq[S];
  constexpr int CL = EMBED * L;
  for (int idx = tid; idx < CL * 32; idx += THREADS) {
    const int b   = idx / CL;
    const int rem = idx - b * CL;
    const int bg  = min(bbase + b, p.B - 1);
    sX[rem * 33 + b] = xg[(size_t)bg * CL + rem] * 0.2f;
  }
  stage_wpairs(p, sWp, S, tid);
  __syncthreads();
  const ull* sWu = (const ull*)sWp;
  const int bg = min(bbase + lane, p.B - 1);
  conv_long<L, 1>(sX, sWu + 0,    lane, w, S * 80 + 0,  bg, p.B);
  conv_long<L, 3>(sX, sWu + 160,  lane, w, S * 80 + 16, bg, p.B);
  conv_long<L, 5>(sX, sWu + 640,  lane, w, S * 80 + 32, bg, p.B);
  conv_long<L, 7>(sX, sWu + 1440, lane, w, S * 80 + 48, bg, p.B);
  conv_long<L, 9>(sX, sWu + 2560, lane, w, S * 80 + 64, bg, p.B);
}

__global__ __launch_bounds__(THREADS, 2) void conv_kernel(ConvParams p) {
  extern __shared__ float smem[];
  float2* sWp = (float2*)smem;                 // 4000 float2
  float2* sX2 = (float2*)(smem + SWP_F2 * 2);  // dup path
  float*  sX  = smem + SWP_F2 * 2;             // long path
  const int tid   = threadIdx.x;
  const int lane  = tid & 31;
  const int w     = tid >> 5;
  const int bbase = blockIdx.x * 32;
  switch (blockIdx.y) {
    case 0: do_seq_dup <12, 0>(p, sWp, sX2, tid, lane, w, bbase); break;
    case 1: do_seq_dup < 7, 1>(p, sWp, sX2, tid, lane, w, bbase); break;
    case 2: do_seq_dup < 8, 2>(p, sWp, sX2, tid, lane, w, bbase); break;
    case 3: do_seq_long<16, 3>(p, sWp, sX,  tid, lane, w, bbase); break;
    case 4: do_seq_dup < 6, 4>(p, sWp, sX2, tid, lane, w, bbase); break;
    case 5: do_seq_dup < 7, 5>(p, sWp, sX2, tid, lane, w, bbase); break;
    case 6: do_seq_long<18, 6>(p, sWp, sX,  tid, lane, w, bbase); break;
  }
}

// ---------------- W1 pre-pack: g_w1p[i*32+col] = (W1[2col][i], W1[2col+1][i])
__global__ void prep_w1_kernel(const float* __restrict__ w1) {
  const int idx = blockIdx.x * 256 + threadIdx.x;
  if (idx < FEAT * 32) {
    const int i   = idx >> 5;
    const int col = idx & 31;
    g_w1p[idx] = make_float2(w1[(size_t)(2 * col) * FEAT + i],
                             w1[(size_t)(2 * col + 1) * FEAT + i]);
  }
}

// ---------------- MLP: 64 batch per CTA, 2 batch/thread, f32x2 ----------
constexpr int MLP_SMEM_BYTES = 64 * 65 * 4;

__global__ __launch_bounds__(THREADS) void mlp_kernel(MlpParams p) {
  extern __shared__ float sH[];   // [64 batch][65]
  const int tid   = threadIdx.x;
  const int lane  = tid & 31;
  const int g     = tid >> 5;     // warp -> hidden cols g*8 .. g*8+7
  const int bbase = blockIdx.x * 64;
  const int b0 = min(bbase + lane, p.B - 1);
  const int b1 = min(b0 + 32, p.B - 1);

  ull acc0[4], acc1[4];
  #pragma unroll
  for (int pp = 0; pp < 4; ++pp) {
    const ull bia = pack2(p.lin1_b[g * 8 + 2 * pp], p.lin1_b[g * 8 + 2 * pp + 1]);
    acc0[pp] = bia; acc1[pp] = bia;
  }

  const float4* wbase = (const float4*)(g_w1p);
  #pragma unroll 4
  for (int i = 0; i < FEAT; ++i) {
    const float f0 = g_feat[(size_t)i * p.B + b0];
    const float f1 = g_feat[(size_t)i * p.B + b1];
    const ull ff0 = pack2(f0, f0);
    const ull ff1 = pack2(f1, f1);
    const float4 wa = wbase[i * 16 + g * 2];
    const float4 wb = wbase[i * 16 + g * 2 + 1];
    const ull w0  = pack2(wa.x, wa.y);
    const ull w1v = pack2(wa.z, wa.w);
    const ull w2  = pack2(wb.x, wb.y);
    const ull w3  = pack2(wb.z, wb.w);
    acc0[0] = fma2(ff0, w0, acc0[0]);  acc1[0] = fma2(ff1, w0, acc1[0]);
    acc0[1] = fma2(ff0, w1v, acc0[1]); acc1[1] = fma2(ff1, w1v, acc1[1]);
    acc0[2] = fma2(ff0, w2, acc0[2]);  acc1[2] = fma2(ff1, w2, acc1[2]);
    acc0[3] = fma2(ff0, w3, acc0[3]);  acc1[3] = fma2(ff1, w3, acc1[3]);
  }
  #pragma unroll
  for (int pp = 0; pp < 4; ++pp) {
    float a, b;
    unpack2(acc0[pp], a, b);
    sH[lane * 65 + g * 8 + 2 * pp]     = 1.f / (1.f + __expf(-a));
    sH[lane * 65 + g * 8 + 2 * pp + 1] = 1.f / (1.f + __expf(-b));
    unpack2(acc1[pp], a, b);
    sH[(lane + 32) * 65 + g * 8 + 2 * pp]     = 1.f / (1.f + __expf(-a));
    sH[(lane + 32) * 65 + g * 8 + 2 * pp + 1] = 1.f / (1.f + __expf(-b));
  }
  __syncthreads();

  if (tid < 64) {
    const int bgo = bbase + tid;
    if (bgo < p.B) {
      float o = p.lin2_b[0];
      #pragma unroll
      for (int j = 0; j < 64; ++j)
        o = fmaf(sH[tid * 65 + j], __ldg(p.lin2_w + j), o);
      p.out[bgo] = o;
    }
  }
}

} // namespace

extern "C" void kernel_launch(void* const* d_in, const int* in_sizes, int n_in,
                              void* d_out, int out_size) {
  ConvParams cp;
  for (int i = 0; i < 7; ++i) cp.seq[i] = (const float*)d_in[i];
  for (int j = 0; j < 5; ++j) cp.Wk[j] = (const float*)d_in[7 + j];
  cp.B = out_size;

  MlpParams mp;
  mp.lin1_w = (const float*)d_in[12];
  mp.lin1_b = (const float*)d_in[13];
  mp.lin2_w = (const float*)d_in[14];
  mp.lin2_b = (const float*)d_in[15];
  mp.out = (float*)d_out;
  mp.B   = out_size;

  static bool attr_set = false;
  if (!attr_set) {
    cudaFuncSetAttribute(conv_kernel,
                         cudaFuncAttributeMaxDynamicSharedMemorySize, CONV_SMEM_BYTES);
    attr_set = true;
  }

  const int tiles32 = (cp.B + 31) / 32;
  const int tiles64 = (cp.B + 63) / 64;
  prep_w1_kernel<<<(FEAT * 32 + 255) / 256, 256>>>(mp.lin1_w);
  dim3 cgrid(tiles32, 7);
  conv_kernel<<<cgrid, THREADS, CONV_SMEM_BYTES>>>(cp);
  mlp_kernel<<<tiles64, THREADS, MLP_SMEM_BYTES>>>(mp);
}

// round 5
// speedup vs baseline: 1.2934x; 1.0406x over previous
#include <cuda_runtime.h>
#include <math.h>

namespace {

constexpr int EMBED     = 20;
constexpr int THREADS   = 256;
constexpr int FEAT      = 560;
constexpr int BATCH_MAX = 16384;

typedef unsigned long long ull;

// ---------------- packed f32x2 helpers (Blackwell FFMA2) ----------------
__device__ __forceinline__ ull pack2(float a, float b) {
  ull r;
  asm("mov.b64 %0, {%1, %2};" : "=l"(r) : "f"(a), "f"(b));
  return r;
}
__device__ __forceinline__ void unpack2(ull v, float& a, float& b) {
  asm("mov.b64 {%0, %1}, %2;" : "=f"(a), "=f"(b) : "l"(v));
}
__device__ __forceinline__ ull fma2(ull a, ull b, ull c) {
  ull d;
  asm("fma.rn.f32x2 %0, %1, %2, %3;" : "=l"(d) : "l"(a), "l"(b), "l"(c));
  return d;
}

// ---------------- global scratch ----------------
__device__ float  g_feat[FEAT * BATCH_MAX];   // transposed [feat][B]
__device__ float2 g_w1p[FEAT * 32];           // [i][col]=(W1[2c][i],W1[2c+1][i])

struct ConvParams {
  const float* seq[7];
  const float* Wk[5];
  int B;
};
struct MlpParams {
  const float* lin1_w;
  const float* lin1_b;
  const float* lin2_w;
  const float* lin2_b;
  float* out;
  int B;
};

// smem: x tile only, [c*L+l][33] float2 = (x_b, x_{b+32}); max L = 18
constexpr int CONV_SMEM_BYTES = EMBED * 18 * 33 * 8;   // 95040

// ---- one t-chunk of a conv: batch-paired accumulators, regs bounded ----
// wg points at W[f][0][0] for this (seq,ksize,filter): layout [c][j], row K.
template<int L, int K, int T0, int T1>
__device__ __forceinline__ void conv_chunk(const ull* __restrict__ sXu,
                                           const float* __restrict__ wg,
                                           int lane, float& m0, float& m1) {
  constexpr int PAD = (K - 1) / 2;
  constexpr int XLO = (T0 - PAD > 0) ? (T0 - PAD) : 0;
  constexpr int XHI = (T1 + PAD < L) ? (T1 + PAD) : L;   // exclusive
  constexpr int NX  = XHI - XLO;
  constexpr int NT  = T1 - T0;
  ull acc[NT];
  #pragma unroll
  for (int t = 0; t < NT; ++t) acc[t] = 0ULL;
  #pragma unroll 2
  for (int c = 0; c < EMBED; ++c) {
    ull xx[NX];
    #pragma unroll
    for (int l = 0; l < NX; ++l)
      xx[l] = sXu[(c * L + XLO + l) * 33 + lane];        // LDS.64, pairs
    ull wt[K];
    #pragma unroll
    for (int j = 0; j < K; ++j) {
      const float wv = __ldg(wg + c * K + j);            // warp-uniform, L1
      wt[j] = pack2(wv, wv);
    }
    #pragma unroll
    for (int t = T0; t < T1; ++t) {
      #pragma unroll
      for (int j = 0; j < K; ++j) {
        const int xi = t + j - PAD;                      // compile-time pred
        if (xi >= 0 && xi < L)
          acc[t - T0] = fma2(xx[xi - XLO], wt[j], acc[t - T0]);
      }
    }
  }
  #pragma unroll
  for (int t = 0; t < NT; ++t) {
    float a, b; unpack2(acc[t], a, b);
    m0 = fmaxf(m0, a); m1 = fmaxf(m1, b);                // relu+gmax
  }
}

// split positions into chunks of <=6 so register arrays stay small
template<int L, int K>
__device__ __forceinline__ void conv_all(const ull* __restrict__ sXu,
                                         const float* __restrict__ wg,
                                         int lane, float& m0, float& m1) {
  if constexpr (L <= 9) {
    conv_chunk<L, K, 0, L>(sXu, wg, lane, m0, m1);
  } else if constexpr (L <= 12) {
    conv_chunk<L, K, 0, 6>(sXu, wg, lane, m0, m1);
    conv_chunk<L, K, 6, L>(sXu, wg, lane, m0, m1);
  } else {
    conv_chunk<L, K, 0, 6>(sXu, wg, lane, m0, m1);
    conv_chunk<L, K, 6, 12>(sXu, wg, lane, m0, m1);
    conv_chunk<L, K, 12, L>(sXu, wg, lane, m0, m1);
  }
}

template<int L, int S>
__device__ void do_seq(const ConvParams& p, float2* sX2,
                       int tid, int lane, int w, int bbase) {
  // stage x: sX2[rem][bp] = (x[bbase+bp], x[bbase+bp+32]) / 5
  const float* xg = p.seq[S];
  constexpr int CL = EMBED * L;
  for (int idx = tid; idx < CL * 32; idx += THREADS) {
    const int bp  = idx / CL;
    const int rem = idx - bp * CL;
    const int b0  = min(bbase + bp, p.B - 1);
    const int b1  = min(b0 + 32, p.B - 1);
    sX2[rem * 33 + bp] = make_float2(xg[(size_t)b0 * CL + rem] * 0.2f,
                                     xg[(size_t)b1 * CL + rem] * 0.2f);
  }
  __syncthreads();
  const ull* sXu = (const ull*)sX2;
  const int bg0 = min(bbase + lane, p.B - 1);
  const int bg1 = min(bg0 + 32, p.B - 1);

  #pragma unroll
  for (int fi = 0; fi < 2; ++fi) {
    const int f = 2 * w + fi;
    // k = 1
    {
      float m0 = 0.f, m1 = 0.f;
      conv_all<L, 1>(sXu, p.Wk[0] + ((size_t)S * 16 + f) * EMBED * 1, lane, m0, m1);
      g_feat[(size_t)(S * 80 + 0 + f) * p.B + bg0] = m0;
      g_feat[(size_t)(S * 80 + 0 + f) * p.B + bg1] = m1;
    }
    // k = 3
    {
      float m0 = 0.f, m1 = 0.f;
      conv_all<L, 3>(sXu, p.Wk[1] + ((size_t)S * 16 + f) * EMBED * 3, lane, m0, m1);
      g_feat[(size_t)(S * 80 + 16 + f) * p.B + bg0] = m0;
      g_feat[(size_t)(S * 80 + 16 + f) * p.B + bg1] = m1;
    }
    // k = 5
    {
      float m0 = 0.f, m1 = 0.f;
      conv_all<L, 5>(sXu, p.Wk[2] + ((size_t)S * 16 + f) * EMBED * 5, lane, m0, m1);
      g_feat[(size_t)(S * 80 + 32 + f) * p.B + bg0] = m0;
      g_feat[(size_t)(S * 80 + 32 + f) * p.B + bg1] = m1;
    }
    // k = 7
    {
      float m0 = 0.f, m1 = 0.f;
      conv_all<L, 7>(sXu, p.Wk[3] + ((size_t)S * 16 + f) * EMBED * 7, lane, m0, m1);
      g_feat[(size_t)(S * 80 + 48 + f) * p.B + bg0] = m0;
      g_feat[(size_t)(S * 80 + 48 + f) * p.B + bg1] = m1;
    }
    // k = 9
    {
      float m0 = 0.f, m1 = 0.f;
      conv_all<L, 9>(sXu, p.Wk[4] + ((size_t)S * 16 + f) * EMBED * 9, lane, m0, m1);
      g_feat[(size_t)(S * 80 + 64 + f) * p.B + bg0] = m0;
      g_feat[(size_t)(S * 80 + 64 + f) * p.B + bg1] = m1;
    }
  }
}

__global__ __launch_bounds__(THREADS, 2) void conv_kernel(ConvParams p) {
  extern __shared__ float smem[];
  float2* sX2 = (float2*)smem;
  const int tid   = threadIdx.x;
  const int lane  = tid & 31;
  const int w     = tid >> 5;          // warp -> filter pair (2w, 2w+1)
  const int bbase = blockIdx.x * 64;   // 64 batch per CTA (paired)
  switch (blockIdx.y) {
    case 0: do_seq<12, 0>(p, sX2, tid, lane, w, bbase); break;
    case 1: do_seq< 7, 1>(p, sX2, tid, lane, w, bbase); break;
    case 2: do_seq< 8, 2>(p, sX2, tid, lane, w, bbase); break;
    case 3: do_seq<16, 3>(p, sX2, tid, lane, w, bbase); break;
    case 4: do_seq< 6, 4>(p, sX2, tid, lane, w, bbase); break;
    case 5: do_seq< 7, 5>(p, sX2, tid, lane, w, bbase); break;
    case 6: do_seq<18, 6>(p, sX2, tid, lane, w, bbase); break;
  }
}

// ---------------- W1 pre-pack: g_w1p[i*32+col] = (W1[2col][i], W1[2col+1][i])
__global__ void prep_w1_kernel(const float* __restrict__ w1) {
  const int idx = blockIdx.x * 256 + threadIdx.x;
  if (idx < FEAT * 32) {
    const int i   = idx >> 5;
    const int col = idx & 31;
    g_w1p[idx] = make_float2(w1[(size_t)(2 * col) * FEAT + i],
                             w1[(size_t)(2 * col + 1) * FEAT + i]);
  }
}

// ---------------- MLP: 64 batch per CTA, 2 batch/thread, f32x2 ----------
constexpr int MLP_SMEM_BYTES = 64 * 65 * 4;

__global__ __launch_bounds__(THREADS) void mlp_kernel(MlpParams p) {
  extern __shared__ float sH[];   // [64 batch][65]
  const int tid   = threadIdx.x;
  const int lane  = tid & 31;
  const int g     = tid >> 5;     // warp -> hidden cols g*8 .. g*8+7
  const int bbase = blockIdx.x * 64;
  const int b0 = min(bbase + lane, p.B - 1);
  const int b1 = min(b0 + 32, p.B - 1);

  ull acc0[4], acc1[4];
  #pragma unroll
  for (int pp = 0; pp < 4; ++pp) {
    const ull bia = pack2(p.lin1_b[g * 8 + 2 * pp], p.lin1_b[g * 8 + 2 * pp + 1]);
    acc0[pp] = bia; acc1[pp] = bia;
  }

  const float4* wbase = (const float4*)(g_w1p);
  #pragma unroll 4
  for (int i = 0; i < FEAT; ++i) {
    const float f0 = g_feat[(size_t)i * p.B + b0];
    const float f1 = g_feat[(size_t)i * p.B + b1];
    const ull ff0 = pack2(f0, f0);
    const ull ff1 = pack2(f1, f1);
    const float4 wa = wbase[i * 16 + g * 2];
    const float4 wb = wbase[i * 16 + g * 2 + 1];
    const ull w0  = pack2(wa.x, wa.y);
    const ull w1v = pack2(wa.z, wa.w);
    const ull w2  = pack2(wb.x, wb.y);
    const ull w3  = pack2(wb.z, wb.w);
    acc0[0] = fma2(ff0, w0, acc0[0]);  acc1[0] = fma2(ff1, w0, acc1[0]);
    acc0[1] = fma2(ff0, w1v, acc0[1]); acc1[1] = fma2(ff1, w1v, acc1[1]);
    acc0[2] = fma2(ff0, w2, acc0[2]);  acc1[2] = fma2(ff1, w2, acc1[2]);
    acc0[3] = fma2(ff0, w3, acc0[3]);  acc1[3] = fma2(ff1, w3, acc1[3]);
  }
  #pragma unroll
  for (int pp = 0; pp < 4; ++pp) {
    float a, b;
    unpack2(acc0[pp], a, b);
    sH[lane * 65 + g * 8 + 2 * pp]     = 1.f / (1.f + __expf(-a));
    sH[lane * 65 + g * 8 + 2 * pp + 1] = 1.f / (1.f + __expf(-b));
    unpack2(acc1[pp], a, b);
    sH[(lane + 32) * 65 + g * 8 + 2 * pp]     = 1.f / (1.f + __expf(-a));
    sH[(lane + 32) * 65 + g * 8 + 2 * pp + 1] = 1.f / (1.f + __expf(-b));
  }
  __syncthreads();

  if (tid < 64) {
    const int bgo = bbase + tid;
    if (bgo < p.B) {
      float o = p.lin2_b[0];
      #pragma unroll
      for (int j = 0; j < 64; ++j)
        o = fmaf(sH[tid * 65 + j], __ldg(p.lin2_w + j), o);
      p.out[bgo] = o;
    }
  }
}

} // namespace

extern "C" void kernel_launch(void* const* d_in, const int* in_sizes, int n_in,
                              void* d_out, int out_size) {
  ConvParams cp;
  for (int i = 0; i < 7; ++i) cp.seq[i] = (const float*)d_in[i];
  for (int j = 0; j < 5; ++j) cp.Wk[j] = (const float*)d_in[7 + j];
  cp.B = out_size;

  MlpParams mp;
  mp.lin1_w = (const float*)d_in[12];
  mp.lin1_b = (const float*)d_in[13];
  mp.lin2_w = (const float*)d_in[14];
  mp.lin2_b = (const float*)d_in[15];
  mp.out = (float*)d_out;
  mp.B   = out_size;

  static bool attr_set = false;
  if (!attr_set) {
    cudaFuncSetAttribute(conv_kernel,
                         cudaFuncAttributeMaxDynamicSharedMemorySize, CONV_SMEM_BYTES);
    attr_set = true;
  }

  const int tiles64 = (cp.B + 63) / 64;
  prep_w1_kernel<<<(FEAT * 32 + 255) / 256, 256>>>(mp.lin1_w);
  dim3 cgrid(tiles64, 7);
  conv_kernel<<<cgrid, THREADS, CONV_SMEM_BYTES>>>(cp);
  mlp_kernel<<<tiles64, THREADS, MLP_SMEM_BYTES>>>(mp);
}